// round 1
// baseline (speedup 1.0000x reference)
#include <cuda_runtime.h>
#include <math.h>

#define BB   2
#define TT   2048
#define DD   768
#define HH   12
#define HDIM 64
#define NTOK (BB*TT)

// Scratch (no allocations allowed)
__device__ float g_q[(size_t)BB*HH*TT*HDIM];
__device__ float g_k[(size_t)BB*HH*TT*HDIM];
__device__ float g_v[(size_t)BB*HH*TT*HDIM];
__device__ float g_ctx[(size_t)NTOK*DD];

// ---------------------------------------------------------------------------
// Projection GEMM: C[n,m] = sum_k X[n,k]*W[m,k]; out = (C + bias[m]) * scale
// MODE 0: write to [B,H,T,HD] layout (BN==64==HDIM so blockIdx.x == head)
// MODE 1: write flat [n, m]
// Tiles: BM=128 (tokens) x BN=64 (features), BK=16. 256 threads, 8x4/thread.
// ---------------------------------------------------------------------------
template<int MODE>
__global__ __launch_bounds__(256) void proj_kernel(
    const float* __restrict__ X, const float* __restrict__ W,
    const float* __restrict__ bias, float* __restrict__ out, float scale)
{
    __shared__ float As[16][132];   // k-major, padded
    __shared__ float Bs[16][68];    // k-major, padded

    const int tid = threadIdx.x;
    const int tx = tid & 15;        // 16 col groups (4 cols each)
    const int ty = tid >> 4;        // 16 row groups (8 rows each)
    const int bn0 = blockIdx.x * 64;
    const int bm0 = blockIdx.y * 128;

    float acc[8][4];
#pragma unroll
    for (int i = 0; i < 8; i++)
#pragma unroll
        for (int j = 0; j < 4; j++) acc[i][j] = 0.f;

    for (int kt = 0; kt < DD; kt += 16) {
        // Load A tile 128x16 (2 float4 per thread), store transposed
#pragma unroll
        for (int l = 0; l < 2; l++) {
            int idx = tid + l * 256;
            int row = idx >> 2;
            int kc  = (idx & 3) << 2;
            float4 a = *(const float4*)&X[(size_t)(bm0 + row) * DD + kt + kc];
            As[kc + 0][row] = a.x; As[kc + 1][row] = a.y;
            As[kc + 2][row] = a.z; As[kc + 3][row] = a.w;
        }
        // Load B tile 64x16 (1 float4 per thread), store transposed
        {
            int m  = tid >> 2;
            int kc = (tid & 3) << 2;
            float4 w4 = *(const float4*)&W[(size_t)(bn0 + m) * DD + kt + kc];
            Bs[kc + 0][m] = w4.x; Bs[kc + 1][m] = w4.y;
            Bs[kc + 2][m] = w4.z; Bs[kc + 3][m] = w4.w;
        }
        __syncthreads();

#pragma unroll
        for (int k = 0; k < 16; k++) {
            float4 a0 = *(const float4*)&As[k][ty * 8];
            float4 a1 = *(const float4*)&As[k][ty * 8 + 4];
            float4 b4 = *(const float4*)&Bs[k][tx * 4];
            float av[8] = {a0.x, a0.y, a0.z, a0.w, a1.x, a1.y, a1.z, a1.w};
            float bv[4] = {b4.x, b4.y, b4.z, b4.w};
#pragma unroll
            for (int i = 0; i < 8; i++)
#pragma unroll
                for (int j = 0; j < 4; j++)
                    acc[i][j] = fmaf(av[i], bv[j], acc[i][j]);
        }
        __syncthreads();
    }

    float4 bias4 = *(const float4*)&bias[bn0 + tx * 4];
#pragma unroll
    for (int i = 0; i < 8; i++) {
        int n = bm0 + ty * 8 + i;
        float4 o;
        o.x = (acc[i][0] + bias4.x) * scale;
        o.y = (acc[i][1] + bias4.y) * scale;
        o.z = (acc[i][2] + bias4.z) * scale;
        o.w = (acc[i][3] + bias4.w) * scale;
        if (MODE == 0) {
            int b = n >> 11;               // /TT
            int t = n & (TT - 1);
            int h = blockIdx.x;            // BN==64==HDIM
            *(float4*)&out[(((size_t)(b * HH + h) * TT + t)) * HDIM + tx * 4] = o;
        } else {
            *(float4*)&out[(size_t)n * DD + bn0 + tx * 4] = o;
        }
    }
}

// ---------------------------------------------------------------------------
// Flash attention: one block per (b, h, 64-row q tile). 256 threads.
// Online softmax over 32 s-tiles of 64. q already scaled.
// ---------------------------------------------------------------------------
#define ATTN_SMEM ((64*68*2 + 64*64*2) * 4)   // 67584 bytes

__global__ __launch_bounds__(256) void attn_kernel(
    const float* __restrict__ rpb, const float* __restrict__ mask)
{
    extern __shared__ float sm[];
    float* Qt = sm;                 // [64 k][68] transposed, padded
    float* Kt = Qt + 64 * 68;       // [64 k][68]
    float* Vs = Kt + 64 * 68;       // [64 s][64 hd]
    float* Ps = Vs + 64 * 64;       // [64 t][64 s]

    const int tid = threadIdx.x;
    const int tx = tid & 15;        // 16 col groups of 4
    const int ty = tid >> 4;        // 16 row groups of 4
    const int t0 = blockIdx.x * 64;
    const int h  = blockIdx.y;
    const int b  = blockIdx.z;
    const size_t headbase = ((size_t)(b * HH + h) * TT) * HDIM;

    // Load Q transposed (lanes walk k -> coalesced global, conflict-light STS)
#pragma unroll
    for (int i = 0; i < 16; i++) {
        int idx = tid + i * 256;
        int r = idx >> 6, k = idx & 63;
        Qt[k * 68 + r] = g_q[headbase + (size_t)(t0 + r) * HDIM + k];
    }

    float m_i[4], l_i[4], acc[4][4];
#pragma unroll
    for (int i = 0; i < 4; i++) {
        m_i[i] = -INFINITY; l_i[i] = 0.f;
#pragma unroll
        for (int j = 0; j < 4; j++) acc[i][j] = 0.f;
    }

    const float* rpb_base  = rpb  + (size_t)h * TT * TT;
    const float* mask_base = mask + (size_t)b * TT * TT;

    for (int st = 0; st < TT; st += 64) {
        __syncthreads();   // previous PV done before overwriting tiles
        // K transposed
#pragma unroll
        for (int i = 0; i < 16; i++) {
            int idx = tid + i * 256;
            int r = idx >> 6, k = idx & 63;
            Kt[k * 68 + r] = g_k[headbase + (size_t)(st + r) * HDIM + k];
        }
        // V natural
#pragma unroll
        for (int i = 0; i < 4; i++) {
            int idx = tid + i * 256;
            int r = idx >> 4, c = (idx & 15) << 2;
            *(float4*)&Vs[r * 64 + c] =
                *(const float4*)&g_v[headbase + (size_t)(st + r) * HDIM + c];
        }
        __syncthreads();

        // S = Q K^T  (4x4 per thread)
        float s[4][4];
#pragma unroll
        for (int i = 0; i < 4; i++)
#pragma unroll
            for (int j = 0; j < 4; j++) s[i][j] = 0.f;
#pragma unroll
        for (int k = 0; k < 64; k++) {
            float4 a  = *(const float4*)&Qt[k * 68 + ty * 4];
            float4 bk = *(const float4*)&Kt[k * 68 + tx * 4];
            float av[4] = {a.x, a.y, a.z, a.w};
            float bv[4] = {bk.x, bk.y, bk.z, bk.w};
#pragma unroll
            for (int i = 0; i < 4; i++)
#pragma unroll
                for (int j = 0; j < 4; j++)
                    s[i][j] = fmaf(av[i], bv[j], s[i][j]);
        }

        // bias + mask + online softmax
#pragma unroll
        for (int i = 0; i < 4; i++) {
            int tg = t0 + ty * 4 + i;
            float4 bi = *(const float4*)&rpb_base [(size_t)tg * TT + st + tx * 4];
            float4 mk = *(const float4*)&mask_base[(size_t)tg * TT + st + tx * 4];
            s[i][0] += bi.x + mk.x;
            s[i][1] += bi.y + mk.y;
            s[i][2] += bi.z + mk.z;
            s[i][3] += bi.w + mk.w;

            float r = fmaxf(fmaxf(s[i][0], s[i][1]), fmaxf(s[i][2], s[i][3]));
            r = fmaxf(r, __shfl_xor_sync(0xffffffffu, r, 1));
            r = fmaxf(r, __shfl_xor_sync(0xffffffffu, r, 2));
            r = fmaxf(r, __shfl_xor_sync(0xffffffffu, r, 4));
            r = fmaxf(r, __shfl_xor_sync(0xffffffffu, r, 8));

            float mn    = fmaxf(m_i[i], r);
            float alpha = __expf(m_i[i] - mn);
            float p0 = __expf(s[i][0] - mn);
            float p1 = __expf(s[i][1] - mn);
            float p2 = __expf(s[i][2] - mn);
            float p3 = __expf(s[i][3] - mn);
            float rs = p0 + p1 + p2 + p3;
            rs += __shfl_xor_sync(0xffffffffu, rs, 1);
            rs += __shfl_xor_sync(0xffffffffu, rs, 2);
            rs += __shfl_xor_sync(0xffffffffu, rs, 4);
            rs += __shfl_xor_sync(0xffffffffu, rs, 8);

            l_i[i] = l_i[i] * alpha + rs;
            m_i[i] = mn;
#pragma unroll
            for (int j = 0; j < 4; j++) acc[i][j] *= alpha;

            float4 pq = {p0, p1, p2, p3};
            *(float4*)&Ps[(ty * 4 + i) * 64 + tx * 4] = pq;
        }
        __syncthreads();

        // O += P V
#pragma unroll 8
        for (int sc = 0; sc < 64; sc++) {
            float4 vv = *(const float4*)&Vs[sc * 64 + tx * 4];
#pragma unroll
            for (int i = 0; i < 4; i++) {
                float p = Ps[(ty * 4 + i) * 64 + sc];
                acc[i][0] = fmaf(p, vv.x, acc[i][0]);
                acc[i][1] = fmaf(p, vv.y, acc[i][1]);
                acc[i][2] = fmaf(p, vv.z, acc[i][2]);
                acc[i][3] = fmaf(p, vv.w, acc[i][3]);
            }
        }
    }

    // normalize + write context in [B, T, D] layout
#pragma unroll
    for (int i = 0; i < 4; i++) {
        float inv = 1.0f / l_i[i];
        int tg = t0 + ty * 4 + i;
        float4 o = {acc[i][0] * inv, acc[i][1] * inv,
                    acc[i][2] * inv, acc[i][3] * inv};
        *(float4*)&g_ctx[((size_t)(b * TT) + tg) * DD + h * HDIM + tx * 4] = o;
    }
}

// ---------------------------------------------------------------------------
extern "C" void kernel_launch(void* const* d_in, const int* in_sizes, int n_in,
                              void* d_out, int out_size)
{
    const float* hs   = (const float*)d_in[0];
    const float* mask = (const float*)d_in[1];
    const float* rpb  = (const float*)d_in[2];
    const float* Wq   = (const float*)d_in[3];
    const float* bq   = (const float*)d_in[4];
    const float* Wk   = (const float*)d_in[5];
    const float* bk   = (const float*)d_in[6];
    const float* Wv   = (const float*)d_in[7];
    const float* bv   = (const float*)d_in[8];
    const float* Wo   = (const float*)d_in[9];
    const float* bo   = (const float*)d_in[10];
    float* out = (float*)d_out;

    float *qp, *kp, *vp, *cp;
    cudaGetSymbolAddress((void**)&qp, g_q);
    cudaGetSymbolAddress((void**)&kp, g_k);
    cudaGetSymbolAddress((void**)&vp, g_v);
    cudaGetSymbolAddress((void**)&cp, g_ctx);

    cudaFuncSetAttribute(attn_kernel,
                         cudaFuncAttributeMaxDynamicSharedMemorySize, ATTN_SMEM);

    const float scale = 0.125f;   // HD^-0.5
    dim3 pg(DD / 64, NTOK / 128);

    proj_kernel<0><<<pg, 256>>>(hs, Wq, bq, qp, scale);
    proj_kernel<0><<<pg, 256>>>(hs, Wk, bk, kp, 1.0f);
    proj_kernel<0><<<pg, 256>>>(hs, Wv, bv, vp, 1.0f);

    dim3 ag(TT / 64, HH, BB);
    attn_kernel<<<ag, 256, ATTN_SMEM>>>(rpb, mask);

    proj_kernel<1><<<pg, 256>>>(cp, Wo, bo, out, 1.0f);
}

// round 3
// speedup vs baseline: 1.2768x; 1.2768x over previous
#include <cuda_runtime.h>
#include <cuda_bf16.h>
#include <stdint.h>
#include <math.h>

#define BB   2
#define TT   2048
#define DD   768
#define HH   12
#define HDIM 64
#define NTOK (BB*TT)

typedef __nv_bfloat16 bf16;

// ---------------- scratch (no allocs allowed) ----------------
__device__ float g_q[(size_t)BB*HH*TT*HDIM];
__device__ float g_k[(size_t)BB*HH*TT*HDIM];
__device__ float g_v[(size_t)BB*HH*TT*HDIM];
__device__ float g_ctx[(size_t)NTOK*DD];
__device__ bf16  g_xhi[(size_t)NTOK*DD],  g_xlo[(size_t)NTOK*DD];
__device__ bf16  g_chi[(size_t)NTOK*DD],  g_clo[(size_t)NTOK*DD];
__device__ bf16  g_whi[(size_t)3*DD*DD],  g_wlo[(size_t)3*DD*DD];
__device__ bf16  g_wohi[(size_t)DD*DD],   g_wolo[(size_t)DD*DD];

// ---------------- helpers ----------------
__device__ __forceinline__ uint32_t smem_u32(const void* p) {
    uint32_t a;
    asm("{ .reg .u64 t; cvta.to.shared.u64 t, %1; cvt.u32.u64 %0, t; }"
        : "=r"(a) : "l"(p));
    return a;
}
#define CP16(saddr, gptr) \
    asm volatile("cp.async.cg.shared.global [%0], [%1], 16;" :: "r"(saddr), "l"(gptr))
#define CP_COMMIT() asm volatile("cp.async.commit_group;" ::: "memory")
#define CP_WAIT1()  asm volatile("cp.async.wait_group 1;" ::: "memory")
#define CP_WAIT0()  asm volatile("cp.async.wait_group 0;" ::: "memory")

__device__ __forceinline__ void ldm_x4(uint32_t* r, uint32_t addr) {
    asm volatile("ldmatrix.sync.aligned.m8n8.x4.shared.b16 {%0,%1,%2,%3}, [%4];"
                 : "=r"(r[0]), "=r"(r[1]), "=r"(r[2]), "=r"(r[3]) : "r"(addr));
}
__device__ __forceinline__ void mma16816(float* d, const uint32_t* a, const uint32_t* b) {
    asm volatile(
        "mma.sync.aligned.m16n8k16.row.col.f32.bf16.bf16.f32 "
        "{%0,%1,%2,%3}, {%4,%5,%6,%7}, {%8,%9}, {%0,%1,%2,%3};"
        : "+f"(d[0]), "+f"(d[1]), "+f"(d[2]), "+f"(d[3])
        : "r"(a[0]), "r"(a[1]), "r"(a[2]), "r"(a[3]), "r"(b[0]), "r"(b[1]));
}

// ---------------- split fp32 -> bf16 hi/lo ----------------
__global__ __launch_bounds__(256) void split_kernel(
    const float* __restrict__ x, bf16* __restrict__ hi, bf16* __restrict__ lo, int n4)
{
    int i = blockIdx.x * 256 + threadIdx.x;
    if (i >= n4) return;
    float4 v = ((const float4*)x)[i];
    bf16 h0 = __float2bfloat16(v.x), h1 = __float2bfloat16(v.y);
    bf16 h2 = __float2bfloat16(v.z), h3 = __float2bfloat16(v.w);
    bf16 l0 = __float2bfloat16(v.x - __bfloat162float(h0));
    bf16 l1 = __float2bfloat16(v.y - __bfloat162float(h1));
    bf16 l2 = __float2bfloat16(v.z - __bfloat162float(h2));
    bf16 l3 = __float2bfloat16(v.w - __bfloat162float(h3));
    __nv_bfloat162* H = (__nv_bfloat162*)hi;
    __nv_bfloat162* L = (__nv_bfloat162*)lo;
    H[2*i]   = __nv_bfloat162(h0, h1);  H[2*i+1] = __nv_bfloat162(h2, h3);
    L[2*i]   = __nv_bfloat162(l0, l1);  L[2*i+1] = __nv_bfloat162(l2, l3);
}

// ---------------- HMMA (mma.sync) projection GEMM ----------------
// C[m,n] = sum_k X[m,k]*W[n,k] + bias[n]; split-bf16 (hi*hi + hi*lo + lo*hi),
// fp32 accum. Block 128x128xK32, 8 warps (4M x 2N), warp tile 32x64.
// smem rows padded to 40 bf16 (80B stride -> conflict-free ldmatrix).
#define BKC        32
#define KITERS     (DD / BKC)          // 24
#define LDSS       40                  // bf16 per smem row
#define HALF_BYTES (128 * LDSS * 2)    // 10240 B: one 128x32 half-tile
#define STAGE_BYTES (4 * HALF_BYTES)   // Ahi,Alo,Bhi,Blo
#define PROJ_SMEM  (2 * STAGE_BYTES)   // 81920

struct POut { const float* bias[3]; float* out[3]; };

template<int MODE>   // 0: out [B,H,T,HD], scale 0.125 for z==0; 1: flat [m,768]
__global__ __launch_bounds__(256) void proj_mma(
    const bf16* __restrict__ Xhi, const bf16* __restrict__ Xlo,
    const bf16* __restrict__ Whi, const bf16* __restrict__ Wlo, POut po)
{
    extern __shared__ char smem[];
    const int tid = threadIdx.x;
    const int wid = tid >> 5, l = tid & 31;
    const int wm = wid >> 1, wn = wid & 1;
    const int m0 = blockIdx.x * 128;
    const int n0 = blockIdx.y * 128;
    const int z  = blockIdx.z;
    const bf16* Wh = Whi + (size_t)z * DD * DD;
    const bf16* Wl = Wlo + (size_t)z * DD * DD;
    const float* bias = po.bias[z];
    float* out = po.out[z];

    const uint32_t sb = smem_u32(smem);

    // per-lane ldmatrix base offsets (bytes, within a stage)
    const int lg = l >> 3, lr = l & 7;
    const uint32_t a_lb = (uint32_t)((wm * 32 + (lg & 1) * 8 + lr) * 80 + (lg >> 1) * 16);
    const uint32_t b_lb = (uint32_t)((wn * 64 + (lg >> 1) * 8 + lr) * 80 + (lg & 1) * 16)
                          + 2 * HALF_BYTES;

    // per-thread cp.async source/dest (row, chunk) pairs
    float acc[2][8][4];
#pragma unroll
    for (int mt = 0; mt < 2; mt++)
#pragma unroll
        for (int nt = 0; nt < 8; nt++)
#pragma unroll
            for (int r = 0; r < 4; r++) acc[mt][nt][r] = 0.f;

    auto load_stage = [&](int j, int s) {
        const int kt = j * BKC;
        const uint32_t sbase = sb + s * STAGE_BYTES;
#pragma unroll
        for (int t = 0; t < 2; t++) {
            int id  = tid + t * 256;
            int row = id >> 2, ch = id & 3;
            uint32_t so = (uint32_t)(row * 80 + ch * 16);
            size_t go = (size_t)row * DD + kt + ch * 8;
            CP16(sbase + so,                  Xhi + (size_t)m0 * DD + go);
            CP16(sbase + HALF_BYTES + so,     Xlo + (size_t)m0 * DD + go);
            CP16(sbase + 2*HALF_BYTES + so,   Wh  + (size_t)n0 * DD + go);
            CP16(sbase + 3*HALF_BYTES + so,   Wl  + (size_t)n0 * DD + go);
        }
        CP_COMMIT();
    };

    load_stage(0, 0);

    for (int j = 0; j < KITERS; j++) {
        const int buf = j & 1;
        if (j + 1 < KITERS) { load_stage(j + 1, buf ^ 1); CP_WAIT1(); }
        else                { CP_WAIT0(); }
        __syncthreads();

        const uint32_t ab = sb + buf * STAGE_BYTES;
#pragma unroll
        for (int ks = 0; ks < 2; ks++) {
            uint32_t ah[2][4], al[2][4];
#pragma unroll
            for (int mt = 0; mt < 2; mt++) {
                uint32_t aa = ab + a_lb + mt * (16 * 80) + ks * 32;
                ldm_x4(ah[mt], aa);
                ldm_x4(al[mt], aa + HALF_BYTES);
            }
#pragma unroll
            for (int nt2 = 0; nt2 < 4; nt2++) {
                uint32_t bh[4], bl[4];
                uint32_t ba = ab + b_lb + nt2 * (16 * 80) + ks * 32;
                ldm_x4(bh, ba);
                ldm_x4(bl, ba + HALF_BYTES);
#pragma unroll
                for (int mt = 0; mt < 2; mt++) {
                    mma16816(acc[mt][2*nt2],   ah[mt], bh);
                    mma16816(acc[mt][2*nt2],   ah[mt], bl);
                    mma16816(acc[mt][2*nt2],   al[mt], bh);
                    mma16816(acc[mt][2*nt2+1], ah[mt], bh + 2);
                    mma16816(acc[mt][2*nt2+1], ah[mt], bl + 2);
                    mma16816(acc[mt][2*nt2+1], al[mt], bh + 2);
                }
            }
        }
        __syncthreads();
    }

    // epilogue: direct fp32 stores (float2 per row-half)
    const float scale = (MODE == 0 && z == 0) ? 0.125f : 1.0f;
#pragma unroll
    for (int mt = 0; mt < 2; mt++) {
        int row0 = m0 + wm * 32 + mt * 16 + (l >> 2);
#pragma unroll
        for (int nt = 0; nt < 8; nt++) {
            int col = n0 + wn * 64 + nt * 8 + (l & 3) * 2;
            float b0 = bias[col], b1 = bias[col + 1];
#pragma unroll
            for (int hf = 0; hf < 2; hf++) {
                int row = row0 + hf * 8;
                float2 v;
                v.x = (acc[mt][nt][hf * 2 + 0] + b0) * scale;
                v.y = (acc[mt][nt][hf * 2 + 1] + b1) * scale;
                if (MODE == 0) {
                    int b = row >> 11, t = row & (TT - 1);
                    int h = col >> 6, hd = col & 63;
                    *(float2*)&out[(((size_t)(b * HH + h) << 11) + t) * HDIM + hd] = v;
                } else {
                    *(float2*)&out[(size_t)row * DD + col] = v;
                }
            }
        }
    }
}

// ---------------- flash attention (unchanged from R1) ----------------
#define ATTN_SMEM ((64*68*2 + 64*64*2) * 4)

__global__ __launch_bounds__(256) void attn_kernel(
    const float* __restrict__ rpb, const float* __restrict__ mask)
{
    extern __shared__ float sm[];
    float* Qt = sm;
    float* Kt = Qt + 64 * 68;
    float* Vs = Kt + 64 * 68;
    float* Ps = Vs + 64 * 64;

    const int tid = threadIdx.x;
    const int tx = tid & 15;
    const int ty = tid >> 4;
    const int t0 = blockIdx.x * 64;
    const int h  = blockIdx.y;
    const int b  = blockIdx.z;
    const size_t headbase = ((size_t)(b * HH + h) * TT) * HDIM;

#pragma unroll
    for (int i = 0; i < 16; i++) {
        int idx = tid + i * 256;
        int r = idx >> 6, k = idx & 63;
        Qt[k * 68 + r] = g_q[headbase + (size_t)(t0 + r) * HDIM + k];
    }

    float m_i[4], l_i[4], acc[4][4];
#pragma unroll
    for (int i = 0; i < 4; i++) {
        m_i[i] = -INFINITY; l_i[i] = 0.f;
#pragma unroll
        for (int j = 0; j < 4; j++) acc[i][j] = 0.f;
    }

    const float* rpb_base  = rpb  + (size_t)h * TT * TT;
    const float* mask_base = mask + (size_t)b * TT * TT;

    for (int st = 0; st < TT; st += 64) {
        __syncthreads();
#pragma unroll
        for (int i = 0; i < 16; i++) {
            int idx = tid + i * 256;
            int r = idx >> 6, k = idx & 63;
            Kt[k * 68 + r] = g_k[headbase + (size_t)(st + r) * HDIM + k];
        }
#pragma unroll
        for (int i = 0; i < 4; i++) {
            int idx = tid + i * 256;
            int r = idx >> 4, c = (idx & 15) << 2;
            *(float4*)&Vs[r * 64 + c] =
                *(const float4*)&g_v[headbase + (size_t)(st + r) * HDIM + c];
        }
        __syncthreads();

        float s[4][4];
#pragma unroll
        for (int i = 0; i < 4; i++)
#pragma unroll
            for (int j = 0; j < 4; j++) s[i][j] = 0.f;
#pragma unroll
        for (int k = 0; k < 64; k++) {
            float4 a  = *(const float4*)&Qt[k * 68 + ty * 4];
            float4 bk = *(const float4*)&Kt[k * 68 + tx * 4];
            float av[4] = {a.x, a.y, a.z, a.w};
            float bv[4] = {bk.x, bk.y, bk.z, bk.w};
#pragma unroll
            for (int i = 0; i < 4; i++)
#pragma unroll
                for (int j = 0; j < 4; j++)
                    s[i][j] = fmaf(av[i], bv[j], s[i][j]);
        }

#pragma unroll
        for (int i = 0; i < 4; i++) {
            int tg = t0 + ty * 4 + i;
            float4 bi = *(const float4*)&rpb_base [(size_t)tg * TT + st + tx * 4];
            float4 mk = *(const float4*)&mask_base[(size_t)tg * TT + st + tx * 4];
            s[i][0] += bi.x + mk.x;
            s[i][1] += bi.y + mk.y;
            s[i][2] += bi.z + mk.z;
            s[i][3] += bi.w + mk.w;

            float r = fmaxf(fmaxf(s[i][0], s[i][1]), fmaxf(s[i][2], s[i][3]));
            r = fmaxf(r, __shfl_xor_sync(0xffffffffu, r, 1));
            r = fmaxf(r, __shfl_xor_sync(0xffffffffu, r, 2));
            r = fmaxf(r, __shfl_xor_sync(0xffffffffu, r, 4));
            r = fmaxf(r, __shfl_xor_sync(0xffffffffu, r, 8));

            float mn    = fmaxf(m_i[i], r);
            float alpha = __expf(m_i[i] - mn);
            float p0 = __expf(s[i][0] - mn);
            float p1 = __expf(s[i][1] - mn);
            float p2 = __expf(s[i][2] - mn);
            float p3 = __expf(s[i][3] - mn);
            float rs = p0 + p1 + p2 + p3;
            rs += __shfl_xor_sync(0xffffffffu, rs, 1);
            rs += __shfl_xor_sync(0xffffffffu, rs, 2);
            rs += __shfl_xor_sync(0xffffffffu, rs, 4);
            rs += __shfl_xor_sync(0xffffffffu, rs, 8);

            l_i[i] = l_i[i] * alpha + rs;
            m_i[i] = mn;
#pragma unroll
            for (int j = 0; j < 4; j++) acc[i][j] *= alpha;

            float4 pq = {p0, p1, p2, p3};
            *(float4*)&Ps[(ty * 4 + i) * 64 + tx * 4] = pq;
        }
        __syncthreads();

#pragma unroll 8
        for (int sc = 0; sc < 64; sc++) {
            float4 vv = *(const float4*)&Vs[sc * 64 + tx * 4];
#pragma unroll
            for (int i = 0; i < 4; i++) {
                float p = Ps[(ty * 4 + i) * 64 + sc];
                acc[i][0] = fmaf(p, vv.x, acc[i][0]);
                acc[i][1] = fmaf(p, vv.y, acc[i][1]);
                acc[i][2] = fmaf(p, vv.z, acc[i][2]);
                acc[i][3] = fmaf(p, vv.w, acc[i][3]);
            }
        }
    }

#pragma unroll
    for (int i = 0; i < 4; i++) {
        float inv = 1.0f / l_i[i];
        int tg = t0 + ty * 4 + i;
        float4 o = {acc[i][0] * inv, acc[i][1] * inv,
                    acc[i][2] * inv, acc[i][3] * inv};
        *(float4*)&g_ctx[((size_t)(b * TT) + tg) * DD + h * HDIM + tx * 4] = o;
    }
}

// ---------------------------------------------------------------------------
extern "C" void kernel_launch(void* const* d_in, const int* in_sizes, int n_in,
                              void* d_out, int out_size)
{
    const float* hs   = (const float*)d_in[0];
    const float* mask = (const float*)d_in[1];
    const float* rpb  = (const float*)d_in[2];
    const float* Wq   = (const float*)d_in[3];
    const float* bq   = (const float*)d_in[4];
    const float* Wk   = (const float*)d_in[5];
    const float* bk   = (const float*)d_in[6];
    const float* Wv   = (const float*)d_in[7];
    const float* bv   = (const float*)d_in[8];
    const float* Wo   = (const float*)d_in[9];
    const float* bo   = (const float*)d_in[10];
    float* out = (float*)d_out;

    float *qp, *kp, *vp, *cp;
    bf16 *xhi, *xlo, *chi, *clo, *whi, *wlo, *wohi, *wolo;
    cudaGetSymbolAddress((void**)&qp,   g_q);
    cudaGetSymbolAddress((void**)&kp,   g_k);
    cudaGetSymbolAddress((void**)&vp,   g_v);
    cudaGetSymbolAddress((void**)&cp,   g_ctx);
    cudaGetSymbolAddress((void**)&xhi,  g_xhi);
    cudaGetSymbolAddress((void**)&xlo,  g_xlo);
    cudaGetSymbolAddress((void**)&chi,  g_chi);
    cudaGetSymbolAddress((void**)&clo,  g_clo);
    cudaGetSymbolAddress((void**)&whi,  g_whi);
    cudaGetSymbolAddress((void**)&wlo,  g_wlo);
    cudaGetSymbolAddress((void**)&wohi, g_wohi);
    cudaGetSymbolAddress((void**)&wolo, g_wolo);

    cudaFuncSetAttribute(attn_kernel,
                         cudaFuncAttributeMaxDynamicSharedMemorySize, ATTN_SMEM);
    cudaFuncSetAttribute(proj_mma<0>,
                         cudaFuncAttributeMaxDynamicSharedMemorySize, PROJ_SMEM);
    cudaFuncSetAttribute(proj_mma<1>,
                         cudaFuncAttributeMaxDynamicSharedMemorySize, PROJ_SMEM);

    const int W4 = DD * DD / 4;
    split_kernel<<<(NTOK*DD/4 + 255)/256, 256>>>(hs, xhi, xlo, NTOK*DD/4);
    split_kernel<<<(W4 + 255)/256, 256>>>(Wq, whi,            wlo,            W4);
    split_kernel<<<(W4 + 255)/256, 256>>>(Wk, whi + DD*DD,    wlo + DD*DD,    W4);
    split_kernel<<<(W4 + 255)/256, 256>>>(Wv, whi + 2*DD*DD,  wlo + 2*DD*DD,  W4);
    split_kernel<<<(W4 + 255)/256, 256>>>(Wo, wohi,           wolo,           W4);

    POut po_qkv;
    po_qkv.bias[0] = bq; po_qkv.bias[1] = bk; po_qkv.bias[2] = bv;
    po_qkv.out[0]  = qp; po_qkv.out[1]  = kp; po_qkv.out[2]  = vp;
    proj_mma<0><<<dim3(NTOK/128, DD/128, 3), 256, PROJ_SMEM>>>(xhi, xlo, whi, wlo, po_qkv);

    dim3 ag(TT / 64, HH, BB);
    attn_kernel<<<ag, 256, ATTN_SMEM>>>(rpb, mask);

    split_kernel<<<(NTOK*DD/4 + 255)/256, 256>>>(cp, chi, clo, NTOK*DD/4);

    POut po_o;
    po_o.bias[0] = bo; po_o.bias[1] = bo; po_o.bias[2] = bo;
    po_o.out[0]  = out; po_o.out[1] = out; po_o.out[2] = out;
    proj_mma<1><<<dim3(NTOK/128, DD/128, 1), 256, PROJ_SMEM>>>(chi, clo, wohi, wolo, po_o);
}

// round 5
// speedup vs baseline: 2.2766x; 1.7830x over previous
#include <cuda_runtime.h>
#include <cuda_bf16.h>
#include <stdint.h>
#include <math.h>

#define BB   2
#define TT   2048
#define DD   768
#define HH   12
#define HDIM 64
#define NTOK (BB*TT)

typedef __nv_bfloat16 bf16;

// ---------------- scratch (no allocs allowed) ----------------
__device__ float g_ctx[(size_t)NTOK*DD];
__device__ bf16  g_xhi[(size_t)NTOK*DD],  g_xlo[(size_t)NTOK*DD];
__device__ bf16  g_chi[(size_t)NTOK*DD],  g_clo[(size_t)NTOK*DD];
__device__ bf16  g_whi[(size_t)3*DD*DD],  g_wlo[(size_t)3*DD*DD];
__device__ bf16  g_wohi[(size_t)DD*DD],   g_wolo[(size_t)DD*DD];
__device__ bf16  g_qhi[(size_t)BB*HH*TT*HDIM], g_qlo[(size_t)BB*HH*TT*HDIM];
__device__ bf16  g_khi[(size_t)BB*HH*TT*HDIM], g_klo[(size_t)BB*HH*TT*HDIM];
__device__ bf16  g_vhi[(size_t)BB*HH*TT*HDIM], g_vlo[(size_t)BB*HH*TT*HDIM];

// ---------------- helpers ----------------
__device__ __forceinline__ uint32_t smem_u32(const void* p) {
    uint32_t a;
    asm("{ .reg .u64 t; cvta.to.shared.u64 t, %1; cvt.u32.u64 %0, t; }"
        : "=r"(a) : "l"(p));
    return a;
}
#define CP16(saddr, gptr) \
    asm volatile("cp.async.cg.shared.global [%0], [%1], 16;" :: "r"(saddr), "l"(gptr))
#define CP_COMMIT() asm volatile("cp.async.commit_group;" ::: "memory")
#define CP_WAIT1()  asm volatile("cp.async.wait_group 1;" ::: "memory")
#define CP_WAIT0()  asm volatile("cp.async.wait_group 0;" ::: "memory")

__device__ __forceinline__ void ldm_x4(uint32_t* r, uint32_t addr) {
    asm volatile("ldmatrix.sync.aligned.m8n8.x4.shared.b16 {%0,%1,%2,%3}, [%4];"
                 : "=r"(r[0]), "=r"(r[1]), "=r"(r[2]), "=r"(r[3]) : "r"(addr));
}
__device__ __forceinline__ void ldm_x4_t(uint32_t* r, uint32_t addr) {
    asm volatile("ldmatrix.sync.aligned.m8n8.x4.trans.shared.b16 {%0,%1,%2,%3}, [%4];"
                 : "=r"(r[0]), "=r"(r[1]), "=r"(r[2]), "=r"(r[3]) : "r"(addr));
}
__device__ __forceinline__ void mma16816(float* d, const uint32_t* a, const uint32_t* b) {
    asm volatile(
        "mma.sync.aligned.m16n8k16.row.col.f32.bf16.bf16.f32 "
        "{%0,%1,%2,%3}, {%4,%5,%6,%7}, {%8,%9}, {%0,%1,%2,%3};"
        : "+f"(d[0]), "+f"(d[1]), "+f"(d[2]), "+f"(d[3])
        : "r"(a[0]), "r"(a[1]), "r"(a[2]), "r"(a[3]), "r"(b[0]), "r"(b[1]));
}
__device__ __forceinline__ void packsplit(uint32_t& hi, uint32_t& lo, float x, float y) {
    __nv_bfloat162 h2 = __floats2bfloat162_rn(x, y);
    float2 f = __bfloat1622float2(h2);
    __nv_bfloat162 l2 = __floats2bfloat162_rn(x - f.x, y - f.y);
    hi = *(uint32_t*)&h2;
    lo = *(uint32_t*)&l2;
}

// ---------------- split fp32 -> bf16 hi/lo ----------------
__global__ __launch_bounds__(256) void split_kernel(
    const float* __restrict__ x, bf16* __restrict__ hi, bf16* __restrict__ lo, int n4)
{
    int i = blockIdx.x * 256 + threadIdx.x;
    if (i >= n4) return;
    float4 v = ((const float4*)x)[i];
    uint32_t h0, l0, h1, l1;
    packsplit(h0, l0, v.x, v.y);
    packsplit(h1, l1, v.z, v.w);
    uint32_t* H = (uint32_t*)hi;
    uint32_t* L = (uint32_t*)lo;
    H[2*i] = h0; H[2*i+1] = h1;
    L[2*i] = l0; L[2*i+1] = l1;
}

// ---------------- HMMA projection GEMM (R3-validated) ----------------
#define BKC        32
#define KITERS     (DD / BKC)
#define HALF_BYTES (128 * 40 * 2)
#define STAGE_BYTES (4 * HALF_BYTES)
#define PROJ_SMEM  (2 * STAGE_BYTES)

struct POut { const float* bias[3]; void* oa[3]; void* ob[3]; };

template<int MODE>   // 0: out bf16 hi/lo [B,H,T,HD], scale 0.125 for z==0; 1: fp32 [m,768]
__global__ __launch_bounds__(256) void proj_mma(
    const bf16* __restrict__ Xhi, const bf16* __restrict__ Xlo,
    const bf16* __restrict__ Whi, const bf16* __restrict__ Wlo, POut po)
{
    extern __shared__ char smem[];
    const int tid = threadIdx.x;
    const int wid = tid >> 5, l = tid & 31;
    const int wm = wid >> 1, wn = wid & 1;
    const int m0 = blockIdx.x * 128;
    const int n0 = blockIdx.y * 128;
    const int z  = blockIdx.z;
    const bf16* Wh = Whi + (size_t)z * DD * DD;
    const bf16* Wl = Wlo + (size_t)z * DD * DD;
    const float* bias = po.bias[z];

    const uint32_t sb = smem_u32(smem);
    const int lg = l >> 3, lr = l & 7;
    const uint32_t a_lb = (uint32_t)((wm * 32 + (lg & 1) * 8 + lr) * 80 + (lg >> 1) * 16);
    const uint32_t b_lb = (uint32_t)((wn * 64 + (lg >> 1) * 8 + lr) * 80 + (lg & 1) * 16)
                          + 2 * HALF_BYTES;

    float acc[2][8][4];
#pragma unroll
    for (int mt = 0; mt < 2; mt++)
#pragma unroll
        for (int nt = 0; nt < 8; nt++)
#pragma unroll
            for (int r = 0; r < 4; r++) acc[mt][nt][r] = 0.f;

    auto load_stage = [&](int j, int s) {
        const int kt = j * BKC;
        const uint32_t sbase = sb + s * STAGE_BYTES;
#pragma unroll
        for (int t = 0; t < 2; t++) {
            int id  = tid + t * 256;
            int row = id >> 2, ch = id & 3;
            uint32_t so = (uint32_t)(row * 80 + ch * 16);
            size_t go = (size_t)row * DD + kt + ch * 8;
            CP16(sbase + so,                  Xhi + (size_t)m0 * DD + go);
            CP16(sbase + HALF_BYTES + so,     Xlo + (size_t)m0 * DD + go);
            CP16(sbase + 2*HALF_BYTES + so,   Wh  + (size_t)n0 * DD + go);
            CP16(sbase + 3*HALF_BYTES + so,   Wl  + (size_t)n0 * DD + go);
        }
        CP_COMMIT();
    };

    load_stage(0, 0);

    for (int j = 0; j < KITERS; j++) {
        const int buf = j & 1;
        if (j + 1 < KITERS) { load_stage(j + 1, buf ^ 1); CP_WAIT1(); }
        else                { CP_WAIT0(); }
        __syncthreads();

        const uint32_t ab = sb + buf * STAGE_BYTES;
#pragma unroll
        for (int ks = 0; ks < 2; ks++) {
            uint32_t ah[2][4], al[2][4];
#pragma unroll
            for (int mt = 0; mt < 2; mt++) {
                uint32_t aa = ab + a_lb + mt * (16 * 80) + ks * 32;
                ldm_x4(ah[mt], aa);
                ldm_x4(al[mt], aa + HALF_BYTES);
            }
#pragma unroll
            for (int nt2 = 0; nt2 < 4; nt2++) {
                uint32_t bh[4], bl[4];
                uint32_t ba = ab + b_lb + nt2 * (16 * 80) + ks * 32;
                ldm_x4(bh, ba);
                ldm_x4(bl, ba + HALF_BYTES);
#pragma unroll
                for (int mt = 0; mt < 2; mt++) {
                    mma16816(acc[mt][2*nt2],   ah[mt], bh);
                    mma16816(acc[mt][2*nt2],   ah[mt], bl);
                    mma16816(acc[mt][2*nt2],   al[mt], bh);
                    mma16816(acc[mt][2*nt2+1], ah[mt], bh + 2);
                    mma16816(acc[mt][2*nt2+1], ah[mt], bl + 2);
                    mma16816(acc[mt][2*nt2+1], al[mt], bh + 2);
                }
            }
        }
        __syncthreads();
    }

    const float scale = (MODE == 0 && z == 0) ? 0.125f : 1.0f;
#pragma unroll
    for (int mt = 0; mt < 2; mt++) {
        int row0 = m0 + wm * 32 + mt * 16 + (l >> 2);
#pragma unroll
        for (int nt = 0; nt < 8; nt++) {
            int col = n0 + wn * 64 + nt * 8 + (l & 3) * 2;
            float b0 = bias[col], b1 = bias[col + 1];
#pragma unroll
            for (int hf = 0; hf < 2; hf++) {
                int row = row0 + hf * 8;
                float vx = (acc[mt][nt][hf * 2 + 0] + b0) * scale;
                float vy = (acc[mt][nt][hf * 2 + 1] + b1) * scale;
                if (MODE == 0) {
                    bf16* ohi = (bf16*)po.oa[z];
                    bf16* olo = (bf16*)po.ob[z];
                    int bb2 = row >> 11, t = row & (TT - 1);
                    int h = col >> 6, hd = col & 63;
                    size_t idx = (((size_t)(bb2 * HH + h) << 11) + t) * HDIM + hd;
                    uint32_t hp, lp;
                    packsplit(hp, lp, vx, vy);
                    *(uint32_t*)&ohi[idx] = hp;
                    *(uint32_t*)&olo[idx] = lp;
                } else {
                    float2 v = {vx, vy};
                    *(float2*)&((float*)po.oa[z])[(size_t)row * DD + col] = v;
                }
            }
        }
    }
}

// ---------------- HMMA flash attention ----------------
// CTA: 128 q rows x (b,h); 8 warps x 16 rows. s-tiles of 128.
#define AROWB 144
#define ATILE (128*AROWB)              // 18432 B per 128x64 bf16 tile
#define ATT_SMEM (10*ATILE)            // Qhi,Qlo + 2 stages x (Khi,Klo,Vhi,Vlo)
#define NSTILE (TT/128)                // 16

__global__ void __launch_bounds__(256, 1) attn_mma(
    const float* __restrict__ rpb, const float* __restrict__ mask)
{
    extern __shared__ char smx[];
    const uint32_t sb = smem_u32(smx);
    const int tid = threadIdx.x, w = tid >> 5, l = tid & 31;
    const int t0 = blockIdx.x * 128;
    const int h = blockIdx.y, b = blockIdx.z;
    const size_t hoff = ((size_t)(b * HH + h) * TT) * HDIM;

    // full 128x64 bf16 tile = 1024 x 16B chunks; 8 threads per 128B row.
    auto cp_tile = [&](uint32_t soff, const bf16* gbase, int grow0) {
#pragma unroll
        for (int i = 0; i < 4; i++) {
            int idx = tid + i * 256;
            int row = idx >> 3, ch = idx & 7;
            CP16(sb + soff + (uint32_t)(row * AROWB + ch * 16),
                 gbase + hoff + (size_t)(grow0 + row) * HDIM + ch * 8);
        }
    };
    auto load_kv = [&](int st, int s) {
        uint32_t o = 2 * ATILE + s * 4 * ATILE;
        cp_tile(o,             g_khi, st);
        cp_tile(o + ATILE,     g_klo, st);
        cp_tile(o + 2 * ATILE, g_vhi, st);
        cp_tile(o + 3 * ATILE, g_vlo, st);
        CP_COMMIT();
    };

    cp_tile(0,     g_qhi, t0);
    cp_tile(ATILE, g_qlo, t0);
    load_kv(0, 0);            // group 0 (includes Q)
    load_kv(128, 1);          // group 1
    CP_WAIT1();               // Q + stage0 ready
    __syncthreads();

    // Q a-frags, resident whole kernel
    uint32_t qh[4][4], ql[4][4];
    {
        const uint32_t qa = sb + (uint32_t)((w * 16 + (l & 7) + ((l >> 3) & 1) * 8) * AROWB
                                            + (l >> 4) * 16);
#pragma unroll
        for (int ks = 0; ks < 4; ks++) {
            ldm_x4(qh[ks], qa + ks * 32);
            ldm_x4(ql[ks], qa + ks * 32 + ATILE);
        }
    }

    float m0 = -INFINITY, m1 = -INFINITY, sl0 = 0.f, sl1 = 0.f;
    float acc[8][4];
#pragma unroll
    for (int nt = 0; nt < 8; nt++)
#pragma unroll
        for (int r = 0; r < 4; r++) acc[nt][r] = 0.f;

    const float* rb0 = rpb  + (size_t)h * TT * TT + (size_t)(t0 + w * 16 + (l >> 2)) * TT
                       + 2 * (l & 3);
    const float* mb0 = mask + (size_t)b * TT * TT + (size_t)(t0 + w * 16 + (l >> 2)) * TT
                       + 2 * (l & 3);

    for (int j = 0; j < NSTILE; j++) {
        if (j > 0) {
            if (j < NSTILE - 1) CP_WAIT1(); else CP_WAIT0();
            __syncthreads();
        }
        const uint32_t stb = sb + 2 * ATILE + (uint32_t)(j & 1) * 4 * ATILE;

        // ---- S = Q K^T (3-MMA split) ----
        float s[16][4];
#pragma unroll
        for (int t = 0; t < 16; t++)
#pragma unroll
            for (int r = 0; r < 4; r++) s[t][r] = 0.f;

        const uint32_t kb = stb + (uint32_t)(((l & 7) + ((l >> 4) << 3)) * AROWB
                                             + ((l >> 3) & 1) * 16);
#pragma unroll
        for (int ng = 0; ng < 8; ng++) {
            uint32_t krow = kb + (uint32_t)(ng * 16 * AROWB);
#pragma unroll
            for (int ks = 0; ks < 4; ks++) {
                uint32_t kh[4], kl[4];
                ldm_x4(kh, krow + ks * 32);
                ldm_x4(kl, krow + ks * 32 + ATILE);
                mma16816(s[2*ng],   qh[ks], kh);
                mma16816(s[2*ng],   qh[ks], kl);
                mma16816(s[2*ng],   ql[ks], kh);
                mma16816(s[2*ng+1], qh[ks], kh + 2);
                mma16816(s[2*ng+1], qh[ks], kl + 2);
                mma16816(s[2*ng+1], ql[ks], kh + 2);
            }
        }

        // ---- bias + mask + online softmax ----
        const float* r0 = rb0 + j * 128;
        const float* m0p = mb0 + j * 128;
#pragma unroll
        for (int t = 0; t < 16; t++) {
            float2 x0 = *(const float2*)(r0 + t * 8);
            float2 y0 = *(const float2*)(m0p + t * 8);
            float2 x1 = *(const float2*)(r0 + 8 * TT + t * 8);
            float2 y1 = *(const float2*)(m0p + 8 * TT + t * 8);
            s[t][0] += x0.x + y0.x;  s[t][1] += x0.y + y0.y;
            s[t][2] += x1.x + y1.x;  s[t][3] += x1.y + y1.y;
        }
        float mx0 = s[0][0], mx1 = s[0][2];
#pragma unroll
        for (int t = 0; t < 16; t++) {
            mx0 = fmaxf(mx0, fmaxf(s[t][0], s[t][1]));
            mx1 = fmaxf(mx1, fmaxf(s[t][2], s[t][3]));
        }
        mx0 = fmaxf(mx0, __shfl_xor_sync(0xffffffffu, mx0, 1));
        mx0 = fmaxf(mx0, __shfl_xor_sync(0xffffffffu, mx0, 2));
        mx1 = fmaxf(mx1, __shfl_xor_sync(0xffffffffu, mx1, 1));
        mx1 = fmaxf(mx1, __shfl_xor_sync(0xffffffffu, mx1, 2));
        float nm0 = fmaxf(m0, mx0), nm1 = fmaxf(m1, mx1);
        float a0 = __expf(m0 - nm0), a1 = __expf(m1 - nm1);
        m0 = nm0; m1 = nm1;
        float rs0 = 0.f, rs1 = 0.f;
#pragma unroll
        for (int t = 0; t < 16; t++) {
            s[t][0] = __expf(s[t][0] - nm0);
            s[t][1] = __expf(s[t][1] - nm0);
            s[t][2] = __expf(s[t][2] - nm1);
            s[t][3] = __expf(s[t][3] - nm1);
            rs0 += s[t][0] + s[t][1];
            rs1 += s[t][2] + s[t][3];
        }
        rs0 += __shfl_xor_sync(0xffffffffu, rs0, 1);
        rs0 += __shfl_xor_sync(0xffffffffu, rs0, 2);
        rs1 += __shfl_xor_sync(0xffffffffu, rs1, 1);
        rs1 += __shfl_xor_sync(0xffffffffu, rs1, 2);
        sl0 = sl0 * a0 + rs0;
        sl1 = sl1 * a1 + rs1;
#pragma unroll
        for (int nt = 0; nt < 8; nt++) {
            acc[nt][0] *= a0; acc[nt][1] *= a0;
            acc[nt][2] *= a1; acc[nt][3] *= a1;
        }

        // ---- pack P into a-frags (hi/lo) ----
        uint32_t ph[8][4], pl[8][4];
#pragma unroll
        for (int kt = 0; kt < 8; kt++) {
            packsplit(ph[kt][0], pl[kt][0], s[2*kt][0],   s[2*kt][1]);
            packsplit(ph[kt][1], pl[kt][1], s[2*kt][2],   s[2*kt][3]);
            packsplit(ph[kt][2], pl[kt][2], s[2*kt+1][0], s[2*kt+1][1]);
            packsplit(ph[kt][3], pl[kt][3], s[2*kt+1][2], s[2*kt+1][3]);
        }

        // ---- O += P V (3-MMA split, V via ldmatrix.trans) ----
        const uint32_t vb = stb + 2 * ATILE
            + (uint32_t)(((l & 7) + ((l >> 3) & 1) * 8) * AROWB + (l >> 4) * 16);
#pragma unroll
        for (int kt = 0; kt < 8; kt++) {
            uint32_t vrow = vb + (uint32_t)(kt * 16 * AROWB);
#pragma unroll
            for (int nv = 0; nv < 4; nv++) {
                uint32_t vh[4], vl[4];
                ldm_x4_t(vh, vrow + nv * 32);
                ldm_x4_t(vl, vrow + nv * 32 + ATILE);
                mma16816(acc[2*nv],   ph[kt], vh);
                mma16816(acc[2*nv],   pl[kt], vh);
                mma16816(acc[2*nv],   ph[kt], vl);
                mma16816(acc[2*nv+1], ph[kt], vh + 2);
                mma16816(acc[2*nv+1], pl[kt], vh + 2);
                mma16816(acc[2*nv+1], ph[kt], vl + 2);
            }
        }

        __syncthreads();
        if (j + 2 < NSTILE) load_kv((j + 2) * 128, j & 1);
    }

    // ---- normalize + write ctx [B,T,D] fp32 ----
    float i0 = 1.f / sl0, i1 = 1.f / sl1;
    int grow = b * TT + t0 + w * 16 + (l >> 2);
    int gcol = h * HDIM + 2 * (l & 3);
#pragma unroll
    for (int nt = 0; nt < 8; nt++) {
        float2 v0 = {acc[nt][0] * i0, acc[nt][1] * i0};
        float2 v1 = {acc[nt][2] * i1, acc[nt][3] * i1};
        *(float2*)&g_ctx[(size_t)grow * DD + gcol + nt * 8] = v0;
        *(float2*)&g_ctx[(size_t)(grow + 8) * DD + gcol + nt * 8] = v1;
    }
}

// ---------------------------------------------------------------------------
extern "C" void kernel_launch(void* const* d_in, const int* in_sizes, int n_in,
                              void* d_out, int out_size)
{
    const float* hs   = (const float*)d_in[0];
    const float* mask = (const float*)d_in[1];
    const float* rpb  = (const float*)d_in[2];
    const float* Wq   = (const float*)d_in[3];
    const float* bq   = (const float*)d_in[4];
    const float* Wk   = (const float*)d_in[5];
    const float* bk   = (const float*)d_in[6];
    const float* Wv   = (const float*)d_in[7];
    const float* bv   = (const float*)d_in[8];
    const float* Wo   = (const float*)d_in[9];
    const float* bo   = (const float*)d_in[10];
    float* out = (float*)d_out;

    float *cp;
    bf16 *xhi, *xlo, *chi, *clo, *whi, *wlo, *wohi, *wolo;
    bf16 *qhi, *qlo, *khi, *klo, *vhi, *vlo;
    cudaGetSymbolAddress((void**)&cp,   g_ctx);
    cudaGetSymbolAddress((void**)&xhi,  g_xhi);
    cudaGetSymbolAddress((void**)&xlo,  g_xlo);
    cudaGetSymbolAddress((void**)&chi,  g_chi);
    cudaGetSymbolAddress((void**)&clo,  g_clo);
    cudaGetSymbolAddress((void**)&whi,  g_whi);
    cudaGetSymbolAddress((void**)&wlo,  g_wlo);
    cudaGetSymbolAddress((void**)&wohi, g_wohi);
    cudaGetSymbolAddress((void**)&wolo, g_wolo);
    cudaGetSymbolAddress((void**)&qhi,  g_qhi);
    cudaGetSymbolAddress((void**)&qlo,  g_qlo);
    cudaGetSymbolAddress((void**)&khi,  g_khi);
    cudaGetSymbolAddress((void**)&klo,  g_klo);
    cudaGetSymbolAddress((void**)&vhi,  g_vhi);
    cudaGetSymbolAddress((void**)&vlo,  g_vlo);

    cudaFuncSetAttribute(proj_mma<0>,
                         cudaFuncAttributeMaxDynamicSharedMemorySize, PROJ_SMEM);
    cudaFuncSetAttribute(proj_mma<1>,
                         cudaFuncAttributeMaxDynamicSharedMemorySize, PROJ_SMEM);
    cudaFuncSetAttribute(attn_mma,
                         cudaFuncAttributeMaxDynamicSharedMemorySize, ATT_SMEM);

    const int W4 = DD * DD / 4;
    split_kernel<<<(NTOK*DD/4 + 255)/256, 256>>>(hs, xhi, xlo, NTOK*DD/4);
    split_kernel<<<(W4 + 255)/256, 256>>>(Wq, whi,            wlo,            W4);
    split_kernel<<<(W4 + 255)/256, 256>>>(Wk, whi + DD*DD,    wlo + DD*DD,    W4);
    split_kernel<<<(W4 + 255)/256, 256>>>(Wv, whi + 2*DD*DD,  wlo + 2*DD*DD,  W4);
    split_kernel<<<(W4 + 255)/256, 256>>>(Wo, wohi,           wolo,           W4);

    POut po_qkv;
    po_qkv.bias[0] = bq; po_qkv.bias[1] = bk; po_qkv.bias[2] = bv;
    po_qkv.oa[0] = qhi; po_qkv.oa[1] = khi; po_qkv.oa[2] = vhi;
    po_qkv.ob[0] = qlo; po_qkv.ob[1] = klo; po_qkv.ob[2] = vlo;
    proj_mma<0><<<dim3(NTOK/128, DD/128, 3), 256, PROJ_SMEM>>>(xhi, xlo, whi, wlo, po_qkv);

    attn_mma<<<dim3(TT/128, HH, BB), 256, ATT_SMEM>>>(rpb, mask);

    split_kernel<<<(NTOK*DD/4 + 255)/256, 256>>>(cp, chi, clo, NTOK*DD/4);

    POut po_o;
    po_o.bias[0] = bo; po_o.bias[1] = bo; po_o.bias[2] = bo;
    po_o.oa[0] = out; po_o.oa[1] = out; po_o.oa[2] = out;
    po_o.ob[0] = out; po_o.ob[1] = out; po_o.ob[2] = out;
    proj_mma<1><<<dim3(NTOK/128, DD/128, 1), 256, PROJ_SMEM>>>(chi, clo, wohi, wolo, po_o);
}